// round 2
// baseline (speedup 1.0000x reference)
#include <cuda_runtime.h>
#include <math.h>

#define Bn 16
#define Cn 64
#define Hn 256
#define Wn 256
#define M0 20
#define M1 20

// Scratch (device globals; allocation-free per harness rules)
__device__ float2 g_tw[256];                 // e^{+2*pi*i*m/256}
__device__ float2 g_T1[Bn*Cn*M1*Hn];         // [b*64+i][kx][y]   fwd-x result
__device__ float2 g_Xf[Bn*M0*M1*Cn];         // [b][ky][kx][i]    fwd-y result
__device__ float2 g_Yf[Bn*M0*M1*Cn];         // [b][ky][kx][o]    mixed
__device__ float2 g_T2[Bn*Cn*Hn*M1];         // [b*64+o][y][kx]   inv-y result (x2 folded for kx>=1)

__global__ void k_init() {
    int m = threadIdx.x;
    double s, c;
    sincospi((double)m / 128.0, &s, &c);     // angle = 2*pi*m/256
    g_tw[m] = make_float2((float)c, (float)s);
}

// ---------------- Kernel 1: forward DFT along x (real input -> 20 complex modes) ----------------
// GEMM: C[262144 rows, 40] = X[rows,256] @ D[256,40], D[x][2kx]=cos, D[x][2kx+1]=-sin
__global__ __launch_bounds__(256) void k_fwdx(const float* __restrict__ x) {
    __shared__ float As[32][257];    // [k][row], pad for conflict-free
    __shared__ float Bs[32][40];
    __shared__ float2 tws[256];
    int tid = threadIdx.x;
    tws[tid] = g_tw[tid];
    int rowBase = blockIdx.x * 256;
    int rowg = tid & 31, colg = tid >> 5;

    float acc[8][5];
#pragma unroll
    for (int r = 0; r < 8; r++)
#pragma unroll
        for (int j = 0; j < 5; j++) acc[r][j] = 0.f;

    for (int kc = 0; kc < 256; kc += 32) {
        __syncthreads();
#pragma unroll
        for (int e = 0; e < 32; e++) {
            int idx = tid + 256 * e;
            int kloc = idx & 31;
            int r = idx >> 5;
            As[kloc][r] = x[(size_t)(rowBase + r) * 256 + kc + kloc];
        }
#pragma unroll
        for (int e = 0; e < 5; e++) {
            int idx = tid + 256 * e;          // 0..1279
            int kloc = idx / 40;
            int j = idx - kloc * 40;
            int kx = j >> 1;
            float2 t = tws[(kx * (kc + kloc)) & 255];
            Bs[kloc][j] = (j & 1) ? -t.y : t.x;
        }
        __syncthreads();
#pragma unroll
        for (int k = 0; k < 32; k++) {
            float a[8], bv[5];
#pragma unroll
            for (int r = 0; r < 8; r++) a[r] = As[k][rowg * 8 + r];
#pragma unroll
            for (int j = 0; j < 5; j++) bv[j] = Bs[k][colg * 5 + j];
#pragma unroll
            for (int r = 0; r < 8; r++)
#pragma unroll
                for (int j = 0; j < 5; j++)
                    acc[r][j] = fmaf(a[r], bv[j], acc[r][j]);
        }
    }
    float* T1f = (float*)g_T1;
#pragma unroll
    for (int r = 0; r < 8; r++) {
        int row = rowBase + rowg * 8 + r;
        int bi = row >> 8, y = row & 255;
#pragma unroll
        for (int j = 0; j < 5; j++) {
            int jj = colg * 5 + j;
            int kx = jj >> 1, part = jj & 1;
            T1f[(((size_t)bi * M1 + kx) * Hn + y) * 2 + part] = acc[r][j];
        }
    }
}

// ---------------- Kernel 2: forward DFT along y (20 complex modes) ----------------
__global__ __launch_bounds__(256) void k_fwdy() {
    __shared__ float2 T1s[M1 * Hn];   // 5120 float2 = 40KB
    __shared__ float2 tws[256];
    int tid = threadIdx.x;
    tws[tid] = g_tw[tid];
    int bi = blockIdx.x;              // b*64+i
    const float2* src = g_T1 + (size_t)bi * (M1 * Hn);
    for (int idx = tid; idx < M1 * Hn; idx += 256) T1s[idx] = src[idx];
    __syncthreads();
    int b = bi >> 6, i = bi & 63;
    for (int t = tid; t < M0 * M1; t += 256) {
        int ky = t / M1, kx = t - ky * M1;
        float re = 0.f, im = 0.f;
        const float2* rowp = T1s + kx * Hn;
        for (int y = 0; y < Hn; y++) {
            float2 v = rowp[y];
            float2 w = tws[(ky * y) & 255];   // e^{-i th} = (w.x, -w.y)
            re = fmaf(v.x, w.x, fmaf(v.y, w.y, re));
            im = fmaf(v.y, w.x, fmaf(-v.x, w.y, im));
        }
        g_Xf[((size_t)(b * M0 + ky) * M1 + kx) * Cn + i] = make_float2(re, im);
    }
}

// ---------------- Kernel 3: complex channel mixing per mode (+ ortho scale) ----------------
__global__ __launch_bounds__(256) void k_mix(const float* __restrict__ wr, const float* __restrict__ wi) {
    __shared__ float2 Ws[Cn * Cn];   // [i*64+o], 32KB
    __shared__ float2 Xs[4][Cn];
    int tid = threadIdx.x;
    int mode = blockIdx.x;           // ky*20+kx
    for (int idx = tid; idx < Cn * Cn; idx += 256) {
        int g = idx * 400 + mode;    // w[i][o][ky][kx], idx = i*64+o
        Ws[idx] = make_float2(wr[g], wi[g]);
    }
    const float SC = 1.0f / 65536.0f;   // both 'ortho' 1/256 factors
    int bsub = tid >> 6, o = tid & 63;
    for (int bb = 0; bb < Bn; bb += 4) {
        __syncthreads();
        Xs[bsub][o] = g_Xf[((size_t)(bb + bsub) * 400 + mode) * Cn + o];
        __syncthreads();
        float re = 0.f, im = 0.f;
#pragma unroll 8
        for (int i = 0; i < Cn; i++) {
            float2 xv = Xs[bsub][i];
            float2 wv = Ws[i * 64 + o];
            re = fmaf(xv.x, wv.x, fmaf(-xv.y, wv.y, re));
            im = fmaf(xv.x, wv.y, fmaf(xv.y, wv.x, im));
        }
        g_Yf[((size_t)(bb + bsub) * 400 + mode) * Cn + o] = make_float2(re * SC, im * SC);
    }
}

// ---------------- Kernel 4: inverse DFT along y (fold Hermitian x2 for kx>=1) ----------------
__global__ __launch_bounds__(256) void k_invy() {
    __shared__ float2 Ys[M0 * M1];
    __shared__ float2 tws[256];
    int tid = threadIdx.x;
    tws[tid] = g_tw[tid];
    int bo = blockIdx.x;             // b*64+o
    int b = bo >> 6, o = bo & 63;
    for (int idx = tid; idx < M0 * M1; idx += 256)
        Ys[idx] = g_Yf[((size_t)b * 400 + idx) * Cn + o];
    __syncthreads();
    int y = tid;
    float2 twy[M0];
#pragma unroll
    for (int ky = 0; ky < M0; ky++) twy[ky] = tws[(ky * y) & 255];  // e^{+i th}
    float2* dst = g_T2 + ((size_t)bo * Hn + y) * M1;
#pragma unroll 4
    for (int kx = 0; kx < M1; kx++) {
        float re = 0.f, im = 0.f;
#pragma unroll
        for (int ky = 0; ky < M0; ky++) {
            float2 v = Ys[ky * M1 + kx];
            float2 w = twy[ky];
            re = fmaf(v.x, w.x, fmaf(-v.y, w.y, re));
            im = fmaf(v.x, w.y, fmaf(v.y, w.x, im));
        }
        float f = (kx == 0) ? 1.f : 2.f;
        dst[kx] = make_float2(re * f, im * f);
    }
}

// ---------------- Kernel 5: inverse DFT along x + bypass conv + GELU ----------------
__device__ __forceinline__ float gelu_tanh(float v) {
    float inner = 0.7978845608028654f * v * (1.0f + 0.044715f * v * v);
    return 0.5f * v * (1.0f + tanhf(inner));
}

__global__ __launch_bounds__(256) void k_final(const float* __restrict__ x,
                                               const float* __restrict__ conv_w,
                                               const float* __restrict__ conv_b,
                                               float* __restrict__ out) {
    extern __shared__ float sm[];
    float*  Xs  = sm;                                   // [64][256] floats
    float*  Ws  = sm + 64 * 256;                        // [i][72] pitch-72 floats
    float2* T2s = (float2*)(sm + 64 * 256 + 64 * 72);   // [o][20]
    float2* tws = T2s + 64 * 20;                        // [256]
    __shared__ float biasS[64];

    int tid = threadIdx.x;
    int b = blockIdx.x >> 8, y = blockIdx.x & 255;

    {
        const float4* xg4 = (const float4*)x;
        float4* Xs4 = (float4*)Xs;
#pragma unroll
        for (int e = 0; e < 16; e++) {
            int idx = tid + 256 * e;                    // 0..4095
            int i = idx >> 6, c4 = idx & 63;
            Xs4[idx] = xg4[((size_t)(b * 64 + i) * 256 + y) * 64 + c4];
        }
    }
    for (int idx = tid; idx < 4096; idx += 256) {       // conv_w[o][i] -> Ws[i][o]
        int o = idx >> 6, i = idx & 63;
        Ws[i * 72 + o] = conv_w[idx];
    }
    for (int idx = tid; idx < 1280; idx += 256) {
        int o = idx / 20, kxx = idx - o * 20;
        T2s[idx] = g_T2[((size_t)(b * 64 + o) * Hn + y) * M1 + kxx];
    }
    tws[tid] = g_tw[tid];
    if (tid < 64) biasS[tid] = conv_b[tid];
    __syncthreads();

    int tx = tid & 31, ty = tid >> 5;
    int x0 = tx << 3, o0 = ty << 3;

    float acc[8][8];
#pragma unroll
    for (int oo = 0; oo < 8; oo++) {
        float bv = biasS[o0 + oo];
#pragma unroll
        for (int xx = 0; xx < 8; xx++) acc[oo][xx] = bv;
    }

    // bypass: 1x1 conv, 8x8 register tile
#pragma unroll 4
    for (int i = 0; i < 64; i++) {
        float4 xa = *(const float4*)(Xs + i * 256 + x0);
        float4 xb = *(const float4*)(Xs + i * 256 + x0 + 4);
        float4 wa = *(const float4*)(Ws + i * 72 + o0);
        float4 wb = *(const float4*)(Ws + i * 72 + o0 + 4);
        float xv[8] = {xa.x, xa.y, xa.z, xa.w, xb.x, xb.y, xb.z, xb.w};
        float wv[8] = {wa.x, wa.y, wa.z, wa.w, wb.x, wb.y, wb.z, wb.w};
#pragma unroll
        for (int oo = 0; oo < 8; oo++)
#pragma unroll
            for (int xx = 0; xx < 8; xx++)
                acc[oo][xx] = fmaf(wv[oo], xv[xx], acc[oo][xx]);
    }

    // spectral: spec = sum_kx Re(T2[o][kx] * e^{+2 pi i kx x / 256}); rotation recurrence per x-col
    float2 rot[8], rtr[8];
#pragma unroll
    for (int j = 0; j < 8; j++) {
        rot[j] = make_float2(1.f, 0.f);
        rtr[j] = tws[(x0 + j) & 255];
    }
#pragma unroll 4
    for (int kx = 0; kx < 20; kx++) {
        float2 tv[8];
#pragma unroll
        for (int oo = 0; oo < 8; oo++) tv[oo] = T2s[(o0 + oo) * 20 + kx];
#pragma unroll
        for (int oo = 0; oo < 8; oo++)
#pragma unroll
            for (int xx = 0; xx < 8; xx++)
                acc[oo][xx] = fmaf(tv[oo].x, rot[xx].x, fmaf(-tv[oo].y, rot[xx].y, acc[oo][xx]));
#pragma unroll
        for (int j = 0; j < 8; j++) {
            float nx = rot[j].x * rtr[j].x - rot[j].y * rtr[j].y;
            float ny = rot[j].x * rtr[j].y + rot[j].y * rtr[j].x;
            rot[j] = make_float2(nx, ny);
        }
    }

#pragma unroll
    for (int oo = 0; oo < 8; oo++) {
        float4 s0, s1;
        s0.x = gelu_tanh(acc[oo][0]); s0.y = gelu_tanh(acc[oo][1]);
        s0.z = gelu_tanh(acc[oo][2]); s0.w = gelu_tanh(acc[oo][3]);
        s1.x = gelu_tanh(acc[oo][4]); s1.y = gelu_tanh(acc[oo][5]);
        s1.z = gelu_tanh(acc[oo][6]); s1.w = gelu_tanh(acc[oo][7]);
        size_t ob = (((size_t)(b * 64 + o0 + oo)) * 256 + y) * 256 + x0;
        *(float4*)(out + ob) = s0;
        *(float4*)(out + ob + 4) = s1;
    }
}

extern "C" void kernel_launch(void* const* d_in, const int* in_sizes, int n_in,
                              void* d_out, int out_size) {
    const float* x  = (const float*)d_in[0];
    const float* wr = (const float*)d_in[1];
    const float* wi = (const float*)d_in[2];
    const float* cw = (const float*)d_in[3];
    const float* cb = (const float*)d_in[4];
    float* out = (float*)d_out;

    size_t smemBytes = (size_t)(64 * 256 + 64 * 72) * sizeof(float) +
                       (size_t)(64 * 20 + 256) * sizeof(float2);   // 96256 B
    cudaFuncSetAttribute(k_final, cudaFuncAttributeMaxDynamicSharedMemorySize, (int)smemBytes);

    k_init<<<1, 256>>>();
    k_fwdx<<<Bn * Cn * Hn / 256, 256>>>(x);      // 1024 blocks
    k_fwdy<<<Bn * Cn, 256>>>();                  // 1024 blocks
    k_mix<<<M0 * M1, 256>>>(wr, wi);             // 400 blocks
    k_invy<<<Bn * Cn, 256>>>();                  // 1024 blocks
    k_final<<<Bn * Hn, 256, smemBytes>>>(x, cw, cb, out);  // 4096 blocks
}

// round 5
// speedup vs baseline: 1.5753x; 1.5753x over previous
#include <cuda_runtime.h>
#include <math.h>

#define Bn 16
#define Cn 64
#define Hn 256
#define Wn 256
#define M0 20
#define M1 20

typedef unsigned long long ull;

// ---- packed f32x2 helpers (Blackwell FFMA2 path, PTX-only) ----
__device__ __forceinline__ ull pk2(float lo, float hi) {
    ull r; asm("mov.b64 %0, {%1,%2};" : "=l"(r) : "f"(lo), "f"(hi)); return r;
}
__device__ __forceinline__ ull bc2(float v) {
    ull r; asm("mov.b64 %0, {%1,%1};" : "=l"(r) : "f"(v)); return r;
}
__device__ __forceinline__ ull ffma2(ull a, ull b, ull c) {
    ull d; asm("fma.rn.f32x2 %0, %1, %2, %3;" : "=l"(d) : "l"(a), "l"(b), "l"(c)); return d;
}
__device__ __forceinline__ ull fmul2(ull a, ull b) {
    ull d; asm("mul.rn.f32x2 %0, %1, %2;" : "=l"(d) : "l"(a), "l"(b)); return d;
}
__device__ __forceinline__ void upk2(ull v, float& lo, float& hi) {
    asm("mov.b64 {%0,%1}, %2;" : "=f"(lo), "=f"(hi) : "l"(v));
}

// Scratch (device globals; allocation-free per harness rules)
__device__ float2 g_tw[256];                 // e^{+2*pi*i*m/256}
__device__ float2 g_T1[Bn*Cn*M1*Hn];         // [b*64+i][kx][y]
__device__ float2 g_Xf[Bn*M0*M1*Cn];         // [b][ky][kx][i]
__device__ float2 g_Yf[Bn*M0*M1*Cn];         // [b][ky][kx][o]
__device__ float2 g_T2[Bn*Cn*Hn*M1];         // [b*64+o][y][kx]

__global__ void k_init() {
    int m = threadIdx.x;
    double s, c;
    sincospi((double)m / 128.0, &s, &c);
    g_tw[m] = make_float2((float)c, (float)s);
}

// ---------------- Kernel 1: forward DFT along x ----------------
// C[262144 rows, 40] = X[rows,256] @ D[256,40]; packed over row-pairs.
__global__ __launch_bounds__(256) void k_fwdx(const float* __restrict__ x) {
    __shared__ float As[32][258];    // pitch 258: 8B-aligned rows, conflict-lite
    __shared__ float Bs[32][40];
    __shared__ float2 tws[256];
    int tid = threadIdx.x;
    tws[tid] = g_tw[tid];
    int rowBase = blockIdx.x * 256;
    int rowg = tid & 31, colg = tid >> 5;

    ull acc[4][5];
#pragma unroll
    for (int r = 0; r < 4; r++)
#pragma unroll
        for (int j = 0; j < 5; j++) acc[r][j] = 0ull;

    for (int kc = 0; kc < 256; kc += 32) {
        __syncthreads();
#pragma unroll
        for (int e = 0; e < 32; e++) {
            int idx = tid + 256 * e;
            int kloc = idx & 31;
            int r = idx >> 5;
            As[kloc][r] = x[(size_t)(rowBase + r) * 256 + kc + kloc];
        }
#pragma unroll
        for (int e = 0; e < 5; e++) {
            int idx = tid + 256 * e;          // 0..1279
            int kloc = idx / 40;
            int j = idx - kloc * 40;
            int kx = j >> 1;
            float2 t = tws[(kx * (kc + kloc)) & 255];
            Bs[kloc][j] = (j & 1) ? -t.y : t.x;
        }
        __syncthreads();
#pragma unroll
        for (int k = 0; k < 32; k++) {
            const ull* Ap = (const ull*)(&As[k][rowg * 8]);
            ull a0 = Ap[0], a1 = Ap[1], a2 = Ap[2], a3 = Ap[3];
            ull bv[5];
#pragma unroll
            for (int j = 0; j < 5; j++) bv[j] = bc2(Bs[k][colg * 5 + j]);
#pragma unroll
            for (int j = 0; j < 5; j++) {
                acc[0][j] = ffma2(a0, bv[j], acc[0][j]);
                acc[1][j] = ffma2(a1, bv[j], acc[1][j]);
                acc[2][j] = ffma2(a2, bv[j], acc[2][j]);
                acc[3][j] = ffma2(a3, bv[j], acc[3][j]);
            }
        }
    }
    float* T1f = (float*)g_T1;
#pragma unroll
    for (int rp = 0; rp < 4; rp++) {
#pragma unroll
        for (int j = 0; j < 5; j++) {
            float lo, hi;
            upk2(acc[rp][j], lo, hi);
            int jj = colg * 5 + j;
            int kx = jj >> 1, part = jj & 1;
            int row0 = rowBase + rowg * 8 + 2 * rp;
            int bi0 = row0 >> 8, y0 = row0 & 255;
            int row1 = row0 + 1;
            int bi1 = row1 >> 8, y1 = row1 & 255;
            T1f[(((size_t)bi0 * M1 + kx) * Hn + y0) * 2 + part] = lo;
            T1f[(((size_t)bi1 * M1 + kx) * Hn + y1) * 2 + part] = hi;
        }
    }
}

// ---------------- Kernel 2: forward DFT along y ----------------
__global__ __launch_bounds__(256) void k_fwdy() {
    __shared__ float2 T1s[M1 * 257];  // pitch 257: break stride-2048B conflicts
    __shared__ float2 tws[256];
    int tid = threadIdx.x;
    tws[tid] = g_tw[tid];
    int bi = blockIdx.x;              // b*64+i
    const float2* src = g_T1 + (size_t)bi * (M1 * Hn);
    for (int idx = tid; idx < M1 * Hn; idx += 256) {
        int kx = idx >> 8, y = idx & 255;
        T1s[kx * 257 + y] = src[idx];
    }
    __syncthreads();
    int b = bi >> 6, i = bi & 63;
    for (int t = tid; t < M0 * M1; t += 256) {
        int ky = t / M1, kx = t - ky * M1;
        float re = 0.f, im = 0.f;
        const float2* rowp = T1s + kx * 257;
#pragma unroll 8
        for (int y = 0; y < Hn; y++) {
            float2 v = rowp[y];
            float2 w = tws[(ky * y) & 255];
            re = fmaf(v.x, w.x, fmaf(v.y, w.y, re));
            im = fmaf(v.y, w.x, fmaf(-v.x, w.y, im));
        }
        g_Xf[((size_t)(b * M0 + ky) * M1 + kx) * Cn + i] = make_float2(re, im);
    }
}

// ---------------- Kernel 3: complex channel mixing per mode ----------------
__global__ __launch_bounds__(256) void k_mix(const float* __restrict__ wr, const float* __restrict__ wi) {
    __shared__ float2 Ws[Cn * Cn];   // 32KB [i*64+o]
    __shared__ float2 Xs[Bn * Cn];   // 8KB  [b*64+i]
    int tid = threadIdx.x;
    int mode = blockIdx.x;
    for (int idx = tid; idx < Cn * Cn; idx += 256) {
        int g = idx * 400 + mode;
        Ws[idx] = make_float2(wr[g], wi[g]);
    }
    for (int idx = tid; idx < Bn * Cn; idx += 256) {
        int b = idx >> 6, i = idx & 63;
        Xs[idx] = g_Xf[((size_t)b * 400 + mode) * Cn + i];
    }
    __syncthreads();
    const float SC = 1.0f / 65536.0f;
    int o = tid & 63, bq = tid >> 6;          // bq 0..3
    float re[4] = {0,0,0,0}, im[4] = {0,0,0,0};
#pragma unroll 8
    for (int i = 0; i < Cn; i++) {
        float2 wv = Ws[i * 64 + o];
#pragma unroll
        for (int q = 0; q < 4; q++) {
            float2 xv = Xs[(q * 4 + bq) * 64 + i];
            re[q] = fmaf(xv.x, wv.x, fmaf(-xv.y, wv.y, re[q]));
            im[q] = fmaf(xv.x, wv.y, fmaf(xv.y, wv.x, im[q]));
        }
    }
#pragma unroll
    for (int q = 0; q < 4; q++) {
        int b = q * 4 + bq;
        g_Yf[((size_t)b * 400 + mode) * Cn + o] = make_float2(re[q] * SC, im[q] * SC);
    }
}

// ---------------- Kernel 4: inverse DFT along y ----------------
__global__ __launch_bounds__(256) void k_invy() {
    __shared__ float2 Ys[M0 * M1];
    __shared__ float2 tws[256];
    int tid = threadIdx.x;
    tws[tid] = g_tw[tid];
    int bo = blockIdx.x;
    int b = bo >> 6, o = bo & 63;
    for (int idx = tid; idx < M0 * M1; idx += 256)
        Ys[idx] = g_Yf[((size_t)b * 400 + idx) * Cn + o];
    __syncthreads();
    int y = tid;
    float2 twy[M0];
#pragma unroll
    for (int ky = 0; ky < M0; ky++) twy[ky] = tws[(ky * y) & 255];
    float2* dst = g_T2 + ((size_t)bo * Hn + y) * M1;
#pragma unroll 4
    for (int kx = 0; kx < M1; kx++) {
        float re = 0.f, im = 0.f;
#pragma unroll
        for (int ky = 0; ky < M0; ky++) {
            float2 v = Ys[ky * M1 + kx];
            float2 w = twy[ky];
            re = fmaf(v.x, w.x, fmaf(-v.y, w.y, re));
            im = fmaf(v.x, w.y, fmaf(v.y, w.x, im));
        }
        float f = (kx == 0) ? 1.f : 2.f;
        dst[kx] = make_float2(re * f, im * f);
    }
}

// ---------------- Kernel 5: inverse x-DFT + bypass + GELU (packed f32x2) ----------------
__device__ __forceinline__ float gelu_tanh(float v) {
    float inner = 0.7978845608028654f * v * (1.0f + 0.044715f * v * v);
    float t;
    asm("tanh.approx.f32 %0, %1;" : "=f"(t) : "f"(inner));
    return 0.5f * v * (1.0f + t);
}

__global__ __launch_bounds__(256, 2) void k_final(const float* __restrict__ x,
                                                  const float* __restrict__ conv_w,
                                                  const float* __restrict__ conv_b,
                                                  float* __restrict__ out) {
    extern __shared__ float sm[];
    float*  Xs  = sm;                                   // [64][256]
    float*  Ws  = sm + 64 * 256;                        // [i][72]
    float2* T2s = (float2*)(sm + 64 * 256 + 64 * 72);   // [o][20]
    float2* tws = T2s + 64 * 20;                        // [256]
    __shared__ float biasS[64];

    int tid = threadIdx.x;
    int b = blockIdx.x >> 8, y = blockIdx.x & 255;

    {
        const float4* xg4 = (const float4*)x;
        float4* Xs4 = (float4*)Xs;
#pragma unroll
        for (int e = 0; e < 16; e++) {
            int idx = tid + 256 * e;
            int i = idx >> 6, c4 = idx & 63;
            Xs4[idx] = xg4[((size_t)(b * 64 + i) * 256 + y) * 64 + c4];
        }
    }
    for (int idx = tid; idx < 4096; idx += 256) {
        int o = idx >> 6, i = idx & 63;
        Ws[i * 72 + o] = conv_w[idx];
    }
    for (int idx = tid; idx < 1280; idx += 256) {
        int o = idx / 20, kxx = idx - o * 20;
        T2s[idx] = g_T2[((size_t)(b * 64 + o) * Hn + y) * M1 + kxx];
    }
    tws[tid] = g_tw[tid];
    if (tid < 64) biasS[tid] = conv_b[tid];
    __syncthreads();

    int tx = tid & 31, ty = tid >> 5;
    int x0 = tx << 3, o0 = ty << 3;

    // acc[oo][p]: packed pair of x-columns (x0+2p, x0+2p+1)
    ull acc[8][4];
#pragma unroll
    for (int oo = 0; oo < 8; oo++) {
        ull bv = bc2(biasS[o0 + oo]);
#pragma unroll
        for (int p = 0; p < 4; p++) acc[oo][p] = bv;
    }

    // bypass: 1x1 conv, FFMA2 over x-pairs
#pragma unroll 4
    for (int i = 0; i < 64; i++) {
        const ull* Xp = (const ull*)(Xs + i * 256 + x0);
        ull xp0 = Xp[0], xp1 = Xp[1], xp2 = Xp[2], xp3 = Xp[3];
        float4 wa = *(const float4*)(Ws + i * 72 + o0);
        float4 wb = *(const float4*)(Ws + i * 72 + o0 + 4);
        float wv[8] = {wa.x, wa.y, wa.z, wa.w, wb.x, wb.y, wb.z, wb.w};
#pragma unroll
        for (int oo = 0; oo < 8; oo++) {
            ull wp = bc2(wv[oo]);
            acc[oo][0] = ffma2(xp0, wp, acc[oo][0]);
            acc[oo][1] = ffma2(xp1, wp, acc[oo][1]);
            acc[oo][2] = ffma2(xp2, wp, acc[oo][2]);
            acc[oo][3] = ffma2(xp3, wp, acc[oo][3]);
        }
    }

    // spectral: packed rotation recurrence over x-pairs
    ull rot_re[4], rot_im[4], rtr_re[4], rtr_im[4];
#pragma unroll
    for (int p = 0; p < 4; p++) {
        rot_re[p] = bc2(1.f);
        rot_im[p] = 0ull;
        float2 t0 = tws[(x0 + 2 * p) & 255];
        float2 t1 = tws[(x0 + 2 * p + 1) & 255];
        rtr_re[p] = pk2(t0.x, t1.x);
        rtr_im[p] = pk2(t0.y, t1.y);
    }
#pragma unroll 4
    for (int kx = 0; kx < 20; kx++) {
#pragma unroll
        for (int oo = 0; oo < 8; oo++) {
            float2 tv = T2s[(o0 + oo) * 20 + kx];
            ull tvx = bc2(tv.x);
            ull ntvy = bc2(-tv.y);
#pragma unroll
            for (int p = 0; p < 4; p++) {
                acc[oo][p] = ffma2(rot_re[p], tvx, acc[oo][p]);
                acc[oo][p] = ffma2(rot_im[p], ntvy, acc[oo][p]);
            }
        }
#pragma unroll
        for (int p = 0; p < 4; p++) {
            ull t1 = fmul2(rot_re[p], rtr_re[p]);
            ull nim = bc2(0.f);
            // nre = rot_re*rtr_re - rot_im*rtr_im
            ull nrtr = fmul2(rot_im[p], rtr_im[p]);
            // compute as t1 - nrtr via fma with -1
            ull nre = ffma2(nrtr, bc2(-1.f), t1);
            ull t2 = fmul2(rot_re[p], rtr_im[p]);
            nim = ffma2(rot_im[p], rtr_re[p], t2);
            rot_re[p] = nre;
            rot_im[p] = nim;
        }
    }

#pragma unroll
    for (int oo = 0; oo < 8; oo++) {
        float v[8];
#pragma unroll
        for (int p = 0; p < 4; p++) upk2(acc[oo][p], v[2 * p], v[2 * p + 1]);
        float4 s0, s1;
        s0.x = gelu_tanh(v[0]); s0.y = gelu_tanh(v[1]);
        s0.z = gelu_tanh(v[2]); s0.w = gelu_tanh(v[3]);
        s1.x = gelu_tanh(v[4]); s1.y = gelu_tanh(v[5]);
        s1.z = gelu_tanh(v[6]); s1.w = gelu_tanh(v[7]);
        size_t ob = (((size_t)(b * 64 + o0 + oo)) * 256 + y) * 256 + x0;
        *(float4*)(out + ob) = s0;
        *(float4*)(out + ob + 4) = s1;
    }
}

extern "C" void kernel_launch(void* const* d_in, const int* in_sizes, int n_in,
                              void* d_out, int out_size) {
    const float* x  = (const float*)d_in[0];
    const float* wr = (const float*)d_in[1];
    const float* wi = (const float*)d_in[2];
    const float* cw = (const float*)d_in[3];
    const float* cb = (const float*)d_in[4];
    float* out = (float*)d_out;

    size_t smemBytes = (size_t)(64 * 256 + 64 * 72) * sizeof(float) +
                       (size_t)(64 * 20 + 256) * sizeof(float2);   // 96256 B
    cudaFuncSetAttribute(k_final, cudaFuncAttributeMaxDynamicSharedMemorySize, (int)smemBytes);

    k_init<<<1, 256>>>();
    k_fwdx<<<Bn * Cn * Hn / 256, 256>>>(x);
    k_fwdy<<<Bn * Cn, 256>>>();
    k_mix<<<M0 * M1, 256>>>(wr, wi);
    k_invy<<<Bn * Cn, 256>>>();
    k_final<<<Bn * Hn, 256, smemBytes>>>(x, cw, cb, out);
}

// round 8
// speedup vs baseline: 2.2010x; 1.3972x over previous
#include <cuda_runtime.h>
#include <math.h>

#define Bn 16
#define Cn 64
#define Hn 256
#define Wn 256
#define M0 20
#define M1 20

typedef unsigned long long ull;

// ---- packed f32x2 helpers (Blackwell FFMA2 path, PTX-only) ----
__device__ __forceinline__ ull pk2(float lo, float hi) {
    ull r; asm("mov.b64 %0, {%1,%2};" : "=l"(r) : "f"(lo), "f"(hi)); return r;
}
__device__ __forceinline__ ull bc2(float v) {
    ull r; asm("mov.b64 %0, {%1,%1};" : "=l"(r) : "f"(v)); return r;
}
__device__ __forceinline__ ull ffma2(ull a, ull b, ull c) {
    ull d; asm("fma.rn.f32x2 %0, %1, %2, %3;" : "=l"(d) : "l"(a), "l"(b), "l"(c)); return d;
}
__device__ __forceinline__ ull fmul2(ull a, ull b) {
    ull d; asm("mul.rn.f32x2 %0, %1, %2;" : "=l"(d) : "l"(a), "l"(b)); return d;
}
__device__ __forceinline__ void upk2(ull v, float& lo, float& hi) {
    asm("mov.b64 {%0,%1}, %2;" : "=f"(lo), "=f"(hi) : "l"(v));
}

// Scratch (device globals; allocation-free per harness rules)
__device__ float2 g_tw[256];                 // e^{+2*pi*i*m/256}
__device__ float2 g_T1[Bn*Cn*M1*Hn];         // [b*64+i][kx][y]
__device__ float2 g_Xf[Bn*M0*M1*Cn];         // [b][ky][kx][i]
__device__ float2 g_Yf[Bn*M0*M1*Cn];         // [b][ky][kx][o]
__device__ float2 g_T2[Bn*Cn*Hn*M1];         // [b*64+o][y][kx]
__device__ float2 g_Wt[M0*M1*Cn*Cn];         // [mode][i*64+o]  pre-transposed weights

__global__ void k_init() {
    int m = threadIdx.x;
    double s, c;
    sincospi((double)m / 128.0, &s, &c);
    g_tw[m] = make_float2((float)c, (float)s);
}

// ---------------- Kernel 0b: transpose weights  w[i][o][m] -> g_Wt[m][i*64+o] ----------------
__global__ __launch_bounds__(256) void k_wt(const float* __restrict__ wr, const float* __restrict__ wi) {
    __shared__ float2 ts[64][51];
    int tid = threadIdx.x;
    int io0 = (blockIdx.x & 63) * 64;        // 64 io-tiles
    int m0  = (blockIdx.x >> 6) * 50;        // 8 m-tiles of 50
    for (int idx = tid; idx < 64 * 50; idx += 256) {
        int r = idx / 50, c = idx - r * 50;
        int g = (io0 + r) * 400 + (m0 + c);
        ts[r][c] = make_float2(wr[g], wi[g]);
    }
    __syncthreads();
    for (int idx = tid; idx < 64 * 50; idx += 256) {
        int mc = idx >> 6, rc = idx & 63;
        g_Wt[(size_t)(m0 + mc) * 4096 + io0 + rc] = ts[rc][mc];
    }
}

// ---------------- Kernel 1: forward DFT along x ----------------
// C[262144 rows, 40] = X[rows,256] @ D[256,40]; packed row-pairs, pair-strided (conflict-free LDS.64)
__global__ __launch_bounds__(256) void k_fwdx(const float* __restrict__ x) {
    __shared__ float As[32][258];
    __shared__ float Bs[32][40];
    __shared__ float2 tws[256];
    int tid = threadIdx.x;
    tws[tid] = g_tw[tid];
    int rowBase = blockIdx.x * 256;
    int rowg = tid & 31, colg = tid >> 5;

    ull acc[4][5];
#pragma unroll
    for (int r = 0; r < 4; r++)
#pragma unroll
        for (int j = 0; j < 5; j++) acc[r][j] = 0ull;

    for (int kc = 0; kc < 256; kc += 32) {
        __syncthreads();
#pragma unroll
        for (int e = 0; e < 32; e++) {
            int idx = tid + 256 * e;
            int kloc = idx & 31;
            int r = idx >> 5;
            As[kloc][r] = x[(size_t)(rowBase + r) * 256 + kc + kloc];
        }
#pragma unroll
        for (int e = 0; e < 5; e++) {
            int idx = tid + 256 * e;          // 0..1279
            int kloc = idx / 40;
            int j = idx - kloc * 40;
            int kx = j >> 1;
            float2 t = tws[(kx * (kc + kloc)) & 255];
            Bs[kloc][j] = (j & 1) ? -t.y : t.x;
        }
        __syncthreads();
#pragma unroll
        for (int k = 0; k < 32; k++) {
            // rows owned: pairs (2*rowg + 64*rp, +1) -> lane-contiguous 8B loads
            const ull* Abase = (const ull*)(&As[k][0]);
            ull a0 = Abase[rowg];
            ull a1 = Abase[rowg + 32];
            ull a2 = Abase[rowg + 64];
            ull a3 = Abase[rowg + 96];
            ull bv[5];
#pragma unroll
            for (int j = 0; j < 5; j++) bv[j] = bc2(Bs[k][colg * 5 + j]);
#pragma unroll
            for (int j = 0; j < 5; j++) {
                acc[0][j] = ffma2(a0, bv[j], acc[0][j]);
                acc[1][j] = ffma2(a1, bv[j], acc[1][j]);
                acc[2][j] = ffma2(a2, bv[j], acc[2][j]);
                acc[3][j] = ffma2(a3, bv[j], acc[3][j]);
            }
        }
    }
    float* T1f = (float*)g_T1;
#pragma unroll
    for (int rp = 0; rp < 4; rp++) {
#pragma unroll
        for (int j = 0; j < 5; j++) {
            float lo, hi;
            upk2(acc[rp][j], lo, hi);
            int jj = colg * 5 + j;
            int kx = jj >> 1, part = jj & 1;
            int row0 = rowBase + 2 * rowg + 64 * rp;
            int bi0 = row0 >> 8, y0 = row0 & 255;
            int row1 = row0 + 1;
            int bi1 = row1 >> 8, y1 = row1 & 255;
            T1f[(((size_t)bi0 * M1 + kx) * Hn + y0) * 2 + part] = lo;
            T1f[(((size_t)bi1 * M1 + kx) * Hn + y1) * 2 + part] = hi;
        }
    }
}

// ---------------- Kernel 2: forward DFT along y ----------------
__global__ __launch_bounds__(256) void k_fwdy() {
    __shared__ float2 T1s[M1 * 257];  // pitch 257: break stride-2048B conflicts
    __shared__ float2 tws[256];
    int tid = threadIdx.x;
    tws[tid] = g_tw[tid];
    int bi = blockIdx.x;              // b*64+i
    const float2* src = g_T1 + (size_t)bi * (M1 * Hn);
    for (int idx = tid; idx < M1 * Hn; idx += 256) {
        int kx = idx >> 8, y = idx & 255;
        T1s[kx * 257 + y] = src[idx];
    }
    __syncthreads();
    int b = bi >> 6, i = bi & 63;
    for (int t = tid; t < M0 * M1; t += 256) {
        int ky = t / M1, kx = t - ky * M1;
        float re = 0.f, im = 0.f;
        const float2* rowp = T1s + kx * 257;
#pragma unroll 8
        for (int y = 0; y < Hn; y++) {
            float2 v = rowp[y];
            float2 w = tws[(ky * y) & 255];
            re = fmaf(v.x, w.x, fmaf(v.y, w.y, re));
            im = fmaf(v.y, w.x, fmaf(-v.x, w.y, im));
        }
        g_Xf[((size_t)(b * M0 + ky) * M1 + kx) * Cn + i] = make_float2(re, im);
    }
}

// ---------------- Kernel 3: complex channel mixing per mode (contiguous Ws via g_Wt) ----------------
__global__ __launch_bounds__(256) void k_mix() {
    __shared__ float2 Ws[Cn * Cn];   // 32KB [i*64+o]
    __shared__ float2 Xs[Bn * Cn];   // 8KB  [b*64+i]
    int tid = threadIdx.x;
    int mode = blockIdx.x;
    const float2* wsrc = g_Wt + (size_t)mode * 4096;
    for (int idx = tid; idx < Cn * Cn; idx += 256)
        Ws[idx] = wsrc[idx];
    for (int idx = tid; idx < Bn * Cn; idx += 256) {
        int b = idx >> 6, i = idx & 63;
        Xs[idx] = g_Xf[((size_t)b * 400 + mode) * Cn + i];
    }
    __syncthreads();
    const float SC = 1.0f / 65536.0f;
    int o = tid & 63, bq = tid >> 6;          // bq 0..3
    float re[4] = {0,0,0,0}, im[4] = {0,0,0,0};
#pragma unroll 8
    for (int i = 0; i < Cn; i++) {
        float2 wv = Ws[i * 64 + o];
#pragma unroll
        for (int q = 0; q < 4; q++) {
            float2 xv = Xs[(q * 4 + bq) * 64 + i];
            re[q] = fmaf(xv.x, wv.x, fmaf(-xv.y, wv.y, re[q]));
            im[q] = fmaf(xv.x, wv.y, fmaf(xv.y, wv.x, im[q]));
        }
    }
#pragma unroll
    for (int q = 0; q < 4; q++) {
        int b = q * 4 + bq;
        g_Yf[((size_t)b * 400 + mode) * Cn + o] = make_float2(re[q] * SC, im[q] * SC);
    }
}

// ---------------- Kernel 4: inverse DFT along y ----------------
__global__ __launch_bounds__(256) void k_invy() {
    __shared__ float2 Ys[M0 * M1];
    __shared__ float2 tws[256];
    int tid = threadIdx.x;
    tws[tid] = g_tw[tid];
    int bo = blockIdx.x;
    int b = bo >> 6, o = bo & 63;
    for (int idx = tid; idx < M0 * M1; idx += 256)
        Ys[idx] = g_Yf[((size_t)b * 400 + idx) * Cn + o];
    __syncthreads();
    int y = tid;
    float2 twy[M0];
#pragma unroll
    for (int ky = 0; ky < M0; ky++) twy[ky] = tws[(ky * y) & 255];
    float2* dst = g_T2 + ((size_t)bo * Hn + y) * M1;
#pragma unroll 4
    for (int kx = 0; kx < M1; kx++) {
        float re = 0.f, im = 0.f;
#pragma unroll
        for (int ky = 0; ky < M0; ky++) {
            float2 v = Ys[ky * M1 + kx];
            float2 w = twy[ky];
            re = fmaf(v.x, w.x, fmaf(-v.y, w.y, re));
            im = fmaf(v.x, w.y, fmaf(v.y, w.x, im));
        }
        float f = (kx == 0) ? 1.f : 2.f;
        dst[kx] = make_float2(re * f, im * f);
    }
}

// ---------------- Kernel 5: inverse x-DFT + bypass + GELU (packed f32x2, conflict-free) ----------------
__device__ __forceinline__ float gelu_tanh(float v) {
    float inner = 0.7978845608028654f * v * (1.0f + 0.044715f * v * v);
    float t;
    asm("tanh.approx.f32 %0, %1;" : "=f"(t) : "f"(inner));
    return 0.5f * v * (1.0f + t);
}

__global__ __launch_bounds__(256, 2) void k_final(const float* __restrict__ x,
                                                  const float* __restrict__ conv_w,
                                                  const float* __restrict__ conv_b,
                                                  float* __restrict__ out) {
    extern __shared__ float sm[];
    float*  Xs  = sm;                                   // [64][256]
    float*  Ws  = sm + 64 * 256;                        // [i][72]
    float2* T2s = (float2*)(sm + 64 * 256 + 64 * 72);   // [o][20]
    float2* tws = T2s + 64 * 20;                        // [256]
    __shared__ float biasS[64];

    int tid = threadIdx.x;
    int b = blockIdx.x >> 8, y = blockIdx.x & 255;

    {
        const float4* xg4 = (const float4*)x;
        float4* Xs4 = (float4*)Xs;
#pragma unroll
        for (int e = 0; e < 16; e++) {
            int idx = tid + 256 * e;
            int i = idx >> 6, c4 = idx & 63;
            Xs4[idx] = xg4[((size_t)(b * 64 + i) * 256 + y) * 64 + c4];
        }
    }
    for (int idx = tid; idx < 4096; idx += 256) {
        int o = idx >> 6, i = idx & 63;
        Ws[i * 72 + o] = conv_w[idx];
    }
    for (int idx = tid; idx < 1280; idx += 256) {
        int o = idx / 20, kxx = idx - o * 20;
        T2s[idx] = g_T2[((size_t)(b * 64 + o) * Hn + y) * M1 + kxx];
    }
    tws[tid] = g_tw[tid];
    if (tid < 64) biasS[tid] = conv_b[tid];
    __syncthreads();

    int tx = tid & 31, ty = tid >> 5;
    int o0 = ty << 3;
    // thread owns x-column pairs: (2*tx + 64*p, 2*tx + 64*p + 1), p = 0..3  (lane-contiguous)

    ull acc[8][4];
#pragma unroll
    for (int oo = 0; oo < 8; oo++) {
        ull bv = bc2(biasS[o0 + oo]);
#pragma unroll
        for (int p = 0; p < 4; p++) acc[oo][p] = bv;
    }

    // bypass: 1x1 conv, FFMA2 over pair-strided x-pairs (conflict-free LDS.64)
#pragma unroll 4
    for (int i = 0; i < 64; i++) {
        const ull* Xp = (const ull*)(Xs + i * 256);
        ull xp0 = Xp[tx];
        ull xp1 = Xp[tx + 32];
        ull xp2 = Xp[tx + 64];
        ull xp3 = Xp[tx + 96];
        float4 wa = *(const float4*)(Ws + i * 72 + o0);
        float4 wb = *(const float4*)(Ws + i * 72 + o0 + 4);
        float wv[8] = {wa.x, wa.y, wa.z, wa.w, wb.x, wb.y, wb.z, wb.w};
#pragma unroll
        for (int oo = 0; oo < 8; oo++) {
            ull wp = bc2(wv[oo]);
            acc[oo][0] = ffma2(xp0, wp, acc[oo][0]);
            acc[oo][1] = ffma2(xp1, wp, acc[oo][1]);
            acc[oo][2] = ffma2(xp2, wp, acc[oo][2]);
            acc[oo][3] = ffma2(xp3, wp, acc[oo][3]);
        }
    }

    // spectral: packed rotation recurrence over x-pairs
    ull rot_re[4], rot_im[4], rtr_re[4], rtr_im[4];
#pragma unroll
    for (int p = 0; p < 4; p++) {
        rot_re[p] = bc2(1.f);
        rot_im[p] = 0ull;
        float2 t0 = tws[2 * tx + 64 * p];
        float2 t1 = tws[2 * tx + 64 * p + 1];
        rtr_re[p] = pk2(t0.x, t1.x);
        rtr_im[p] = pk2(t0.y, t1.y);
    }
#pragma unroll 4
    for (int kx = 0; kx < 20; kx++) {
#pragma unroll
        for (int oo = 0; oo < 8; oo++) {
            float2 tv = T2s[(o0 + oo) * 20 + kx];
            ull tvx = bc2(tv.x);
            ull ntvy = bc2(-tv.y);
#pragma unroll
            for (int p = 0; p < 4; p++) {
                acc[oo][p] = ffma2(rot_re[p], tvx, acc[oo][p]);
                acc[oo][p] = ffma2(rot_im[p], ntvy, acc[oo][p]);
            }
        }
#pragma unroll
        for (int p = 0; p < 4; p++) {
            ull t1 = fmul2(rot_re[p], rtr_re[p]);
            ull nrtr = fmul2(rot_im[p], rtr_im[p]);
            ull nre = ffma2(nrtr, bc2(-1.f), t1);
            ull t2 = fmul2(rot_re[p], rtr_im[p]);
            ull nim = ffma2(rot_im[p], rtr_re[p], t2);
            rot_re[p] = nre;
            rot_im[p] = nim;
        }
    }

#pragma unroll
    for (int oo = 0; oo < 8; oo++) {
        size_t ob = (((size_t)(b * 64 + o0 + oo)) * 256 + y) * 256;
#pragma unroll
        for (int p = 0; p < 4; p++) {
            float lo, hi;
            upk2(acc[oo][p], lo, hi);
            float2 s = make_float2(gelu_tanh(lo), gelu_tanh(hi));
            *(float2*)(out + ob + 2 * tx + 64 * p) = s;
        }
    }
}

extern "C" void kernel_launch(void* const* d_in, const int* in_sizes, int n_in,
                              void* d_out, int out_size) {
    const float* x  = (const float*)d_in[0];
    const float* wr = (const float*)d_in[1];
    const float* wi = (const float*)d_in[2];
    const float* cw = (const float*)d_in[3];
    const float* cb = (const float*)d_in[4];
    float* out = (float*)d_out;

    size_t smemBytes = (size_t)(64 * 256 + 64 * 72) * sizeof(float) +
                       (size_t)(64 * 20 + 256) * sizeof(float2);   // 96256 B
    cudaFuncSetAttribute(k_final, cudaFuncAttributeMaxDynamicSharedMemorySize, (int)smemBytes);

    k_init<<<1, 256>>>();
    k_wt<<<64 * 8, 256>>>(wr, wi);               // weight transpose (runs concurrently w/ fwdx path)
    k_fwdx<<<Bn * Cn * Hn / 256, 256>>>(x);
    k_fwdy<<<Bn * Cn, 256>>>();
    k_mix<<<M0 * M1, 256>>>();
    k_invy<<<Bn * Cn, 256>>>();
    k_final<<<Bn * Hn, 256, smemBytes>>>(x, cw, cb, out);
}

// round 11
// speedup vs baseline: 2.2142x; 1.0060x over previous
#include <cuda_runtime.h>
#include <math.h>

#define Bn 16
#define Cn 64
#define Hn 256
#define Wn 256
#define M0 20
#define M1 20

typedef unsigned long long ull;

// ---- packed f32x2 helpers (Blackwell FFMA2 path, PTX-only) ----
__device__ __forceinline__ ull pk2(float lo, float hi) {
    ull r; asm("mov.b64 %0, {%1,%2};" : "=l"(r) : "f"(lo), "f"(hi)); return r;
}
__device__ __forceinline__ ull bc2(float v) {
    ull r; asm("mov.b64 %0, {%1,%1};" : "=l"(r) : "f"(v)); return r;
}
__device__ __forceinline__ ull ffma2(ull a, ull b, ull c) {
    ull d; asm("fma.rn.f32x2 %0, %1, %2, %3;" : "=l"(d) : "l"(a), "l"(b), "l"(c)); return d;
}
__device__ __forceinline__ ull fmul2(ull a, ull b) {
    ull d; asm("mul.rn.f32x2 %0, %1, %2;" : "=l"(d) : "l"(a), "l"(b)); return d;
}
__device__ __forceinline__ void upk2(ull v, float& lo, float& hi) {
    asm("mov.b64 {%0,%1}, %2;" : "=f"(lo), "=f"(hi) : "l"(v));
}

// Scratch (device globals; allocation-free per harness rules)
__device__ float2 g_tw[256];                 // e^{+2*pi*i*m/256}
__device__ float2 g_T1[Bn*Cn*M1*Hn];         // [b*64+i][kx][y]
__device__ float2 g_Xf[Bn*M0*M1*Cn];         // [b][ky][kx][i]
__device__ float2 g_Yf[Bn*M0*M1*Cn];         // [b][ky][kx][o]
__device__ float2 g_T2[Bn*Cn*Hn*M1];         // [b*64+o][y][kx]
__device__ float2 g_Wt[M0*M1*Cn*Cn];         // [mode][i*64+o]  pre-transposed weights

__global__ void k_init() {
    int m = threadIdx.x;
    double s, c;
    sincospi((double)m / 128.0, &s, &c);
    g_tw[m] = make_float2((float)c, (float)s);
}

// ---------------- Kernel 0b: transpose weights  w[i][o][m] -> g_Wt[m][i*64+o] ----------------
__global__ __launch_bounds__(256) void k_wt(const float* __restrict__ wr, const float* __restrict__ wi) {
    __shared__ float2 ts[64][51];
    int tid = threadIdx.x;
    int io0 = (blockIdx.x & 63) * 64;        // 64 io-tiles
    int m0  = (blockIdx.x >> 6) * 50;        // 8 m-tiles of 50
    for (int idx = tid; idx < 64 * 50; idx += 256) {
        int r = idx / 50, c = idx - r * 50;
        int g = (io0 + r) * 400 + (m0 + c);
        ts[r][c] = make_float2(wr[g], wi[g]);
    }
    __syncthreads();
    for (int idx = tid; idx < 64 * 50; idx += 256) {
        int mc = idx >> 6, rc = idx & 63;
        g_Wt[(size_t)(m0 + mc) * 4096 + io0 + rc] = ts[rc][mc];
    }
}

// ---------------- Kernel 1: forward DFT along x ----------------
// C[262144 rows, 40] = X[rows,256] @ D[256,40]; packed row-pairs, pair-strided (conflict-free LDS.64)
__global__ __launch_bounds__(256) void k_fwdx(const float* __restrict__ x) {
    __shared__ float As[32][258];
    __shared__ float Bs[32][40];
    __shared__ float2 tws[256];
    int tid = threadIdx.x;
    tws[tid] = g_tw[tid];
    int rowBase = blockIdx.x * 256;
    int rowg = tid & 31, colg = tid >> 5;

    ull acc[4][5];
#pragma unroll
    for (int r = 0; r < 4; r++)
#pragma unroll
        for (int j = 0; j < 5; j++) acc[r][j] = 0ull;

    for (int kc = 0; kc < 256; kc += 32) {
        __syncthreads();
#pragma unroll
        for (int e = 0; e < 32; e++) {
            int idx = tid + 256 * e;
            int kloc = idx & 31;
            int r = idx >> 5;
            As[kloc][r] = x[(size_t)(rowBase + r) * 256 + kc + kloc];
        }
#pragma unroll
        for (int e = 0; e < 5; e++) {
            int idx = tid + 256 * e;          // 0..1279
            int kloc = idx / 40;
            int j = idx - kloc * 40;
            int kx = j >> 1;
            float2 t = tws[(kx * (kc + kloc)) & 255];
            Bs[kloc][j] = (j & 1) ? -t.y : t.x;
        }
        __syncthreads();
#pragma unroll
        for (int k = 0; k < 32; k++) {
            // rows owned: pairs (2*rowg + 64*rp, +1) -> lane-contiguous 8B loads
            const ull* Abase = (const ull*)(&As[k][0]);
            ull a0 = Abase[rowg];
            ull a1 = Abase[rowg + 32];
            ull a2 = Abase[rowg + 64];
            ull a3 = Abase[rowg + 96];
            ull bv[5];
#pragma unroll
            for (int j = 0; j < 5; j++) bv[j] = bc2(Bs[k][colg * 5 + j]);
#pragma unroll
            for (int j = 0; j < 5; j++) {
                acc[0][j] = ffma2(a0, bv[j], acc[0][j]);
                acc[1][j] = ffma2(a1, bv[j], acc[1][j]);
                acc[2][j] = ffma2(a2, bv[j], acc[2][j]);
                acc[3][j] = ffma2(a3, bv[j], acc[3][j]);
            }
        }
    }
    float* T1f = (float*)g_T1;
#pragma unroll
    for (int rp = 0; rp < 4; rp++) {
#pragma unroll
        for (int j = 0; j < 5; j++) {
            float lo, hi;
            upk2(acc[rp][j], lo, hi);
            int jj = colg * 5 + j;
            int kx = jj >> 1, part = jj & 1;
            int row0 = rowBase + 2 * rowg + 64 * rp;
            int bi0 = row0 >> 8, y0 = row0 & 255;
            int row1 = row0 + 1;
            int bi1 = row1 >> 8, y1 = row1 & 255;
            T1f[(((size_t)bi0 * M1 + kx) * Hn + y0) * 2 + part] = lo;
            T1f[(((size_t)bi1 * M1 + kx) * Hn + y1) * 2 + part] = hi;
        }
    }
}

// ---------------- Kernel 2: forward DFT along y ----------------
__global__ __launch_bounds__(256) void k_fwdy() {
    __shared__ float2 T1s[M1 * 257];  // pitch 257: break stride-2048B conflicts
    __shared__ float2 tws[256];
    int tid = threadIdx.x;
    tws[tid] = g_tw[tid];
    int bi = blockIdx.x;              // b*64+i
    const float2* src = g_T1 + (size_t)bi * (M1 * Hn);
    for (int idx = tid; idx < M1 * Hn; idx += 256) {
        int kx = idx >> 8, y = idx & 255;
        T1s[kx * 257 + y] = src[idx];
    }
    __syncthreads();
    int b = bi >> 6, i = bi & 63;
    for (int t = tid; t < M0 * M1; t += 256) {
        int ky = t / M1, kx = t - ky * M1;
        float re = 0.f, im = 0.f;
        const float2* rowp = T1s + kx * 257;
#pragma unroll 8
        for (int y = 0; y < Hn; y++) {
            float2 v = rowp[y];
            float2 w = tws[(ky * y) & 255];
            re = fmaf(v.x, w.x, fmaf(v.y, w.y, re));
            im = fmaf(v.y, w.x, fmaf(-v.x, w.y, im));
        }
        g_Xf[((size_t)(b * M0 + ky) * M1 + kx) * Cn + i] = make_float2(re, im);
    }
}

// ---------------- Kernel 3: complex channel mixing per mode (contiguous Ws via g_Wt) ----------------
__global__ __launch_bounds__(256) void k_mix() {
    __shared__ float2 Ws[Cn * Cn];   // 32KB [i*64+o]
    __shared__ float2 Xs[Bn * Cn];   // 8KB  [b*64+i]
    int tid = threadIdx.x;
    int mode = blockIdx.x;
    const float2* wsrc = g_Wt + (size_t)mode * 4096;
    for (int idx = tid; idx < Cn * Cn; idx += 256)
        Ws[idx] = wsrc[idx];
    for (int idx = tid; idx < Bn * Cn; idx += 256) {
        int b = idx >> 6, i = idx & 63;
        Xs[idx] = g_Xf[((size_t)b * 400 + mode) * Cn + i];
    }
    __syncthreads();
    const float SC = 1.0f / 65536.0f;
    int o = tid & 63, bq = tid >> 6;          // bq 0..3
    float re[4] = {0,0,0,0}, im[4] = {0,0,0,0};
#pragma unroll 8
    for (int i = 0; i < Cn; i++) {
        float2 wv = Ws[i * 64 + o];
#pragma unroll
        for (int q = 0; q < 4; q++) {
            float2 xv = Xs[(q * 4 + bq) * 64 + i];
            re[q] = fmaf(xv.x, wv.x, fmaf(-xv.y, wv.y, re[q]));
            im[q] = fmaf(xv.x, wv.y, fmaf(xv.y, wv.x, im[q]));
        }
    }
#pragma unroll
    for (int q = 0; q < 4; q++) {
        int b = q * 4 + bq;
        g_Yf[((size_t)b * 400 + mode) * Cn + o] = make_float2(re[q] * SC, im[q] * SC);
    }
}

// ---------------- Kernel 4: inverse DFT along y ----------------
__global__ __launch_bounds__(256) void k_invy() {
    __shared__ float2 Ys[M0 * M1];
    __shared__ float2 tws[256];
    int tid = threadIdx.x;
    tws[tid] = g_tw[tid];
    int bo = blockIdx.x;
    int b = bo >> 6, o = bo & 63;
    for (int idx = tid; idx < M0 * M1; idx += 256)
        Ys[idx] = g_Yf[((size_t)b * 400 + idx) * Cn + o];
    __syncthreads();
    int y = tid;
    float2 twy[M0];
#pragma unroll
    for (int ky = 0; ky < M0; ky++) twy[ky] = tws[(ky * y) & 255];
    float2* dst = g_T2 + ((size_t)bo * Hn + y) * M1;
#pragma unroll 4
    for (int kx = 0; kx < M1; kx++) {
        float re = 0.f, im = 0.f;
#pragma unroll
        for (int ky = 0; ky < M0; ky++) {
            float2 v = Ys[ky * M1 + kx];
            float2 w = twy[ky];
            re = fmaf(v.x, w.x, fmaf(-v.y, w.y, re));
            im = fmaf(v.x, w.y, fmaf(v.y, w.x, im));
        }
        float f = (kx == 0) ? 1.f : 2.f;
        dst[kx] = make_float2(re * f, im * f);
    }
}

// ---------------- Kernel 5: inverse x-DFT + bypass + GELU (packed f32x2, conflict-free) ----------------
__device__ __forceinline__ float gelu_tanh(float v) {
    float inner = 0.7978845608028654f * v * (1.0f + 0.044715f * v * v);
    float t;
    asm("tanh.approx.f32 %0, %1;" : "=f"(t) : "f"(inner));
    return 0.5f * v * (1.0f + t);
}

__global__ __launch_bounds__(256, 2) void k_final(const float* __restrict__ x,
                                                  const float* __restrict__ conv_w,
                                                  const float* __restrict__ conv_b,
                                                  float* __restrict__ out) {
    extern __shared__ float sm[];
    float*  Xs  = sm;                                   // [64][256]
    float*  Ws  = sm + 64 * 256;                        // [i][72]
    float2* T2s = (float2*)(sm + 64 * 256 + 64 * 72);   // [o][20]
    float2* tws = T2s + 64 * 20;                        // [256]
    __shared__ float biasS[64];

    int tid = threadIdx.x;
    int b = blockIdx.x >> 8, y = blockIdx.x & 255;

    {
        const float4* xg4 = (const float4*)x;
        float4* Xs4 = (float4*)Xs;
#pragma unroll
        for (int e = 0; e < 16; e++) {
            int idx = tid + 256 * e;
            int i = idx >> 6, c4 = idx & 63;
            Xs4[idx] = xg4[((size_t)(b * 64 + i) * 256 + y) * 64 + c4];
        }
    }
    for (int idx = tid; idx < 4096; idx += 256) {
        int o = idx >> 6, i = idx & 63;
        Ws[i * 72 + o] = conv_w[idx];
    }
    for (int idx = tid; idx < 1280; idx += 256) {
        int o = idx / 20, kxx = idx - o * 20;
        T2s[idx] = g_T2[((size_t)(b * 64 + o) * Hn + y) * M1 + kxx];
    }
    tws[tid] = g_tw[tid];
    if (tid < 64) biasS[tid] = conv_b[tid];
    __syncthreads();

    int tx = tid & 31, ty = tid >> 5;
    int o0 = ty << 3;
    // thread owns x-column pairs: (2*tx + 64*p, 2*tx + 64*p + 1), p = 0..3  (lane-contiguous)

    ull acc[8][4];
#pragma unroll
    for (int oo = 0; oo < 8; oo++) {
        ull bv = bc2(biasS[o0 + oo]);
#pragma unroll
        for (int p = 0; p < 4; p++) acc[oo][p] = bv;
    }

    // bypass: 1x1 conv, FFMA2 over pair-strided x-pairs (conflict-free LDS.64)
#pragma unroll 4
    for (int i = 0; i < 64; i++) {
        const ull* Xp = (const ull*)(Xs + i * 256);
        ull xp0 = Xp[tx];
        ull xp1 = Xp[tx + 32];
        ull xp2 = Xp[tx + 64];
        ull xp3 = Xp[tx + 96];
        float4 wa = *(const float4*)(Ws + i * 72 + o0);
        float4 wb = *(const float4*)(Ws + i * 72 + o0 + 4);
        float wv[8] = {wa.x, wa.y, wa.z, wa.w, wb.x, wb.y, wb.z, wb.w};
#pragma unroll
        for (int oo = 0; oo < 8; oo++) {
            ull wp = bc2(wv[oo]);
            acc[oo][0] = ffma2(xp0, wp, acc[oo][0]);
            acc[oo][1] = ffma2(xp1, wp, acc[oo][1]);
            acc[oo][2] = ffma2(xp2, wp, acc[oo][2]);
            acc[oo][3] = ffma2(xp3, wp, acc[oo][3]);
        }
    }

    // spectral: packed rotation recurrence over x-pairs
    ull rot_re[4], rot_im[4], rtr_re[4], rtr_im[4];
#pragma unroll
    for (int p = 0; p < 4; p++) {
        rot_re[p] = bc2(1.f);
        rot_im[p] = 0ull;
        float2 t0 = tws[2 * tx + 64 * p];
        float2 t1 = tws[2 * tx + 64 * p + 1];
        rtr_re[p] = pk2(t0.x, t1.x);
        rtr_im[p] = pk2(t0.y, t1.y);
    }
#pragma unroll 4
    for (int kx = 0; kx < 20; kx++) {
#pragma unroll
        for (int oo = 0; oo < 8; oo++) {
            float2 tv = T2s[(o0 + oo) * 20 + kx];
            ull tvx = bc2(tv.x);
            ull ntvy = bc2(-tv.y);
#pragma unroll
            for (int p = 0; p < 4; p++) {
                acc[oo][p] = ffma2(rot_re[p], tvx, acc[oo][p]);
                acc[oo][p] = ffma2(rot_im[p], ntvy, acc[oo][p]);
            }
        }
#pragma unroll
        for (int p = 0; p < 4; p++) {
            ull t1 = fmul2(rot_re[p], rtr_re[p]);
            ull nrtr = fmul2(rot_im[p], rtr_im[p]);
            ull nre = ffma2(nrtr, bc2(-1.f), t1);
            ull t2 = fmul2(rot_re[p], rtr_im[p]);
            ull nim = ffma2(rot_im[p], rtr_re[p], t2);
            rot_re[p] = nre;
            rot_im[p] = nim;
        }
    }

#pragma unroll
    for (int oo = 0; oo < 8; oo++) {
        size_t ob = (((size_t)(b * 64 + o0 + oo)) * 256 + y) * 256;
#pragma unroll
        for (int p = 0; p < 4; p++) {
            float lo, hi;
            upk2(acc[oo][p], lo, hi);
            float2 s = make_float2(gelu_tanh(lo), gelu_tanh(hi));
            *(float2*)(out + ob + 2 * tx + 64 * p) = s;
        }
    }
}

extern "C" void kernel_launch(void* const* d_in, const int* in_sizes, int n_in,
                              void* d_out, int out_size) {
    const float* x  = (const float*)d_in[0];
    const float* wr = (const float*)d_in[1];
    const float* wi = (const float*)d_in[2];
    const float* cw = (const float*)d_in[3];
    const float* cb = (const float*)d_in[4];
    float* out = (float*)d_out;

    size_t smemBytes = (size_t)(64 * 256 + 64 * 72) * sizeof(float) +
                       (size_t)(64 * 20 + 256) * sizeof(float2);   // 96256 B
    cudaFuncSetAttribute(k_final, cudaFuncAttributeMaxDynamicSharedMemorySize, (int)smemBytes);

    k_init<<<1, 256>>>();
    k_wt<<<64 * 8, 256>>>(wr, wi);               // weight transpose (runs concurrently w/ fwdx path)
    k_fwdx<<<Bn * Cn * Hn / 256, 256>>>(x);
    k_fwdy<<<Bn * Cn, 256>>>();
    k_mix<<<M0 * M1, 256>>>();
    k_invy<<<Bn * Cn, 256>>>();
    k_final<<<Bn * Hn, 256, smemBytes>>>(x, cw, cb, out);
}

// round 13
// speedup vs baseline: 2.2160x; 1.0008x over previous
#include <cuda_runtime.h>
#include <math.h>

#define Bn 16
#define Cn 64
#define Hn 256
#define Wn 256
#define M0 20
#define M1 20

typedef unsigned long long ull;

// ---- packed f32x2 helpers (Blackwell FFMA2 path, PTX-only) ----
__device__ __forceinline__ ull pk2(float lo, float hi) {
    ull r; asm("mov.b64 %0, {%1,%2};" : "=l"(r) : "f"(lo), "f"(hi)); return r;
}
__device__ __forceinline__ ull bc2(float v) {
    ull r; asm("mov.b64 %0, {%1,%1};" : "=l"(r) : "f"(v)); return r;
}
__device__ __forceinline__ ull ffma2(ull a, ull b, ull c) {
    ull d; asm("fma.rn.f32x2 %0, %1, %2, %3;" : "=l"(d) : "l"(a), "l"(b), "l"(c)); return d;
}
__device__ __forceinline__ ull fmul2(ull a, ull b) {
    ull d; asm("mul.rn.f32x2 %0, %1, %2;" : "=l"(d) : "l"(a), "l"(b)); return d;
}
__device__ __forceinline__ void upk2(ull v, float& lo, float& hi) {
    asm("mov.b64 {%0,%1}, %2;" : "=f"(lo), "=f"(hi) : "l"(v));
}

// Scratch (device globals; allocation-free per harness rules)
__device__ float2 g_tw[256];                 // e^{+2*pi*i*m/256}
__device__ float2 g_T1[Bn*Cn*M1*Hn];         // [b*64+i][kx][y]
__device__ float2 g_Xf[Bn*M0*M1*Cn];         // [b][ky][kx][i]
__device__ float2 g_Yf[Bn*M0*M1*Cn];         // [b][ky][kx][o]
__device__ float2 g_T2[Bn*Cn*Hn*M1];         // [b*64+o][y][kx]
__device__ float2 g_Wt[M0*M1*Cn*Cn];         // [mode][i*64+o]  pre-transposed weights

__global__ void k_init() {
    int m = threadIdx.x;
    double s, c;
    sincospi((double)m / 128.0, &s, &c);
    g_tw[m] = make_float2((float)c, (float)s);
}

// ---------------- Kernel 0b: transpose weights  w[i][o][m] -> g_Wt[m][i*64+o] ----------------
__global__ __launch_bounds__(256) void k_wt(const float* __restrict__ wr, const float* __restrict__ wi) {
    __shared__ float2 ts[64][51];
    int tid = threadIdx.x;
    int io0 = (blockIdx.x & 63) * 64;        // 64 io-tiles
    int m0  = (blockIdx.x >> 6) * 50;        // 8 m-tiles of 50
    for (int idx = tid; idx < 64 * 50; idx += 256) {
        int r = idx / 50, c = idx - r * 50;
        int g = (io0 + r) * 400 + (m0 + c);
        ts[r][c] = make_float2(wr[g], wi[g]);
    }
    __syncthreads();
    for (int idx = tid; idx < 64 * 50; idx += 256) {
        int mc = idx >> 6, rc = idx & 63;
        g_Wt[(size_t)(m0 + mc) * 4096 + io0 + rc] = ts[rc][mc];
    }
}

// ---------------- Kernel 1: forward DFT along x ----------------
// C[262144 rows, 40] = X[rows,256] @ D[256,40]; packed row-pairs, pair-strided (conflict-free LDS.64)
__global__ __launch_bounds__(256) void k_fwdx(const float* __restrict__ x) {
    __shared__ float As[32][258];
    __shared__ float Bs[32][40];
    __shared__ float2 tws[256];
    int tid = threadIdx.x;
    tws[tid] = g_tw[tid];
    int rowBase = blockIdx.x * 256;
    int rowg = tid & 31, colg = tid >> 5;

    ull acc[4][5];
#pragma unroll
    for (int r = 0; r < 4; r++)
#pragma unroll
        for (int j = 0; j < 5; j++) acc[r][j] = 0ull;

    for (int kc = 0; kc < 256; kc += 32) {
        __syncthreads();
#pragma unroll
        for (int e = 0; e < 32; e++) {
            int idx = tid + 256 * e;
            int kloc = idx & 31;
            int r = idx >> 5;
            As[kloc][r] = x[(size_t)(rowBase + r) * 256 + kc + kloc];
        }
#pragma unroll
        for (int e = 0; e < 5; e++) {
            int idx = tid + 256 * e;          // 0..1279
            int kloc = idx / 40;
            int j = idx - kloc * 40;
            int kx = j >> 1;
            float2 t = tws[(kx * (kc + kloc)) & 255];
            Bs[kloc][j] = (j & 1) ? -t.y : t.x;
        }
        __syncthreads();
#pragma unroll
        for (int k = 0; k < 32; k++) {
            // rows owned: pairs (2*rowg + 64*rp, +1) -> lane-contiguous 8B loads
            const ull* Abase = (const ull*)(&As[k][0]);
            ull a0 = Abase[rowg];
            ull a1 = Abase[rowg + 32];
            ull a2 = Abase[rowg + 64];
            ull a3 = Abase[rowg + 96];
            ull bv[5];
#pragma unroll
            for (int j = 0; j < 5; j++) bv[j] = bc2(Bs[k][colg * 5 + j]);
#pragma unroll
            for (int j = 0; j < 5; j++) {
                acc[0][j] = ffma2(a0, bv[j], acc[0][j]);
                acc[1][j] = ffma2(a1, bv[j], acc[1][j]);
                acc[2][j] = ffma2(a2, bv[j], acc[2][j]);
                acc[3][j] = ffma2(a3, bv[j], acc[3][j]);
            }
        }
    }
    float* T1f = (float*)g_T1;
#pragma unroll
    for (int rp = 0; rp < 4; rp++) {
#pragma unroll
        for (int j = 0; j < 5; j++) {
            float lo, hi;
            upk2(acc[rp][j], lo, hi);
            int jj = colg * 5 + j;
            int kx = jj >> 1, part = jj & 1;
            int row0 = rowBase + 2 * rowg + 64 * rp;
            int bi0 = row0 >> 8, y0 = row0 & 255;
            int row1 = row0 + 1;
            int bi1 = row1 >> 8, y1 = row1 & 255;
            T1f[(((size_t)bi0 * M1 + kx) * Hn + y0) * 2 + part] = lo;
            T1f[(((size_t)bi1 * M1 + kx) * Hn + y1) * 2 + part] = hi;
        }
    }
}

// ---------------- Kernel 2: forward DFT along y ----------------
__global__ __launch_bounds__(256) void k_fwdy() {
    __shared__ float2 T1s[M1 * 257];  // pitch 257: break stride-2048B conflicts
    __shared__ float2 tws[256];
    int tid = threadIdx.x;
    tws[tid] = g_tw[tid];
    int bi = blockIdx.x;              // b*64+i
    const float2* src = g_T1 + (size_t)bi * (M1 * Hn);
    for (int idx = tid; idx < M1 * Hn; idx += 256) {
        int kx = idx >> 8, y = idx & 255;
        T1s[kx * 257 + y] = src[idx];
    }
    __syncthreads();
    int b = bi >> 6, i = bi & 63;
    for (int t = tid; t < M0 * M1; t += 256) {
        int ky = t / M1, kx = t - ky * M1;
        float re = 0.f, im = 0.f;
        const float2* rowp = T1s + kx * 257;
#pragma unroll 8
        for (int y = 0; y < Hn; y++) {
            float2 v = rowp[y];
            float2 w = tws[(ky * y) & 255];
            re = fmaf(v.x, w.x, fmaf(v.y, w.y, re));
            im = fmaf(v.y, w.x, fmaf(-v.x, w.y, im));
        }
        g_Xf[((size_t)(b * M0 + ky) * M1 + kx) * Cn + i] = make_float2(re, im);
    }
}

// ---------------- Kernel 3: complex channel mixing per mode (contiguous Ws via g_Wt) ----------------
__global__ __launch_bounds__(256) void k_mix() {
    __shared__ float2 Ws[Cn * Cn];   // 32KB [i*64+o]
    __shared__ float2 Xs[Bn * Cn];   // 8KB  [b*64+i]
    int tid = threadIdx.x;
    int mode = blockIdx.x;
    const float2* wsrc = g_Wt + (size_t)mode * 4096;
    for (int idx = tid; idx < Cn * Cn; idx += 256)
        Ws[idx] = wsrc[idx];
    for (int idx = tid; idx < Bn * Cn; idx += 256) {
        int b = idx >> 6, i = idx & 63;
        Xs[idx] = g_Xf[((size_t)b * 400 + mode) * Cn + i];
    }
    __syncthreads();
    const float SC = 1.0f / 65536.0f;
    int o = tid & 63, bq = tid >> 6;          // bq 0..3
    float re[4] = {0,0,0,0}, im[4] = {0,0,0,0};
#pragma unroll 8
    for (int i = 0; i < Cn; i++) {
        float2 wv = Ws[i * 64 + o];
#pragma unroll
        for (int q = 0; q < 4; q++) {
            float2 xv = Xs[(q * 4 + bq) * 64 + i];
            re[q] = fmaf(xv.x, wv.x, fmaf(-xv.y, wv.y, re[q]));
            im[q] = fmaf(xv.x, wv.y, fmaf(xv.y, wv.x, im[q]));
        }
    }
#pragma unroll
    for (int q = 0; q < 4; q++) {
        int b = q * 4 + bq;
        g_Yf[((size_t)b * 400 + mode) * Cn + o] = make_float2(re[q] * SC, im[q] * SC);
    }
}

// ---------------- Kernel 4: inverse DFT along y ----------------
__global__ __launch_bounds__(256) void k_invy() {
    __shared__ float2 Ys[M0 * M1];
    __shared__ float2 tws[256];
    int tid = threadIdx.x;
    tws[tid] = g_tw[tid];
    int bo = blockIdx.x;
    int b = bo >> 6, o = bo & 63;
    for (int idx = tid; idx < M0 * M1; idx += 256)
        Ys[idx] = g_Yf[((size_t)b * 400 + idx) * Cn + o];
    __syncthreads();
    int y = tid;
    float2 twy[M0];
#pragma unroll
    for (int ky = 0; ky < M0; ky++) twy[ky] = tws[(ky * y) & 255];
    float2* dst = g_T2 + ((size_t)bo * Hn + y) * M1;
#pragma unroll 4
    for (int kx = 0; kx < M1; kx++) {
        float re = 0.f, im = 0.f;
#pragma unroll
        for (int ky = 0; ky < M0; ky++) {
            float2 v = Ys[ky * M1 + kx];
            float2 w = twy[ky];
            re = fmaf(v.x, w.x, fmaf(-v.y, w.y, re));
            im = fmaf(v.x, w.y, fmaf(v.y, w.x, im));
        }
        float f = (kx == 0) ? 1.f : 2.f;
        dst[kx] = make_float2(re * f, im * f);
    }
}

// ---------------- Kernel 5: inverse x-DFT + bypass + GELU (packed f32x2, conflict-free) ----------------
__device__ __forceinline__ float gelu_tanh(float v) {
    float inner = 0.7978845608028654f * v * (1.0f + 0.044715f * v * v);
    float t;
    asm("tanh.approx.f32 %0, %1;" : "=f"(t) : "f"(inner));
    return 0.5f * v * (1.0f + t);
}

__global__ __launch_bounds__(256, 2) void k_final(const float* __restrict__ x,
                                                  const float* __restrict__ conv_w,
                                                  const float* __restrict__ conv_b,
                                                  float* __restrict__ out) {
    extern __shared__ float sm[];
    float*  Xs  = sm;                                   // [64][256]
    float*  Ws  = sm + 64 * 256;                        // [i][72]
    float2* T2s = (float2*)(sm + 64 * 256 + 64 * 72);   // [o][20]
    float2* tws = T2s + 64 * 20;                        // [256]
    __shared__ float biasS[64];

    int tid = threadIdx.x;
    int b = blockIdx.x >> 8, y = blockIdx.x & 255;

    {
        const float4* xg4 = (const float4*)x;
        float4* Xs4 = (float4*)Xs;
#pragma unroll
        for (int e = 0; e < 16; e++) {
            int idx = tid + 256 * e;
            int i = idx >> 6, c4 = idx & 63;
            Xs4[idx] = xg4[((size_t)(b * 64 + i) * 256 + y) * 64 + c4];
        }
    }
    for (int idx = tid; idx < 4096; idx += 256) {
        int o = idx >> 6, i = idx & 63;
        Ws[i * 72 + o] = conv_w[idx];
    }
    for (int idx = tid; idx < 1280; idx += 256) {
        int o = idx / 20, kxx = idx - o * 20;
        T2s[idx] = g_T2[((size_t)(b * 64 + o) * Hn + y) * M1 + kxx];
    }
    tws[tid] = g_tw[tid];
    if (tid < 64) biasS[tid] = conv_b[tid];
    __syncthreads();

    int tx = tid & 31, ty = tid >> 5;
    int o0 = ty << 3;
    // thread owns x-column pairs: (2*tx + 64*p, 2*tx + 64*p + 1), p = 0..3  (lane-contiguous)

    ull acc[8][4];
#pragma unroll
    for (int oo = 0; oo < 8; oo++) {
        ull bv = bc2(biasS[o0 + oo]);
#pragma unroll
        for (int p = 0; p < 4; p++) acc[oo][p] = bv;
    }

    // bypass: 1x1 conv, FFMA2 over pair-strided x-pairs (conflict-free LDS.64)
#pragma unroll 4
    for (int i = 0; i < 64; i++) {
        const ull* Xp = (const ull*)(Xs + i * 256);
        ull xp0 = Xp[tx];
        ull xp1 = Xp[tx + 32];
        ull xp2 = Xp[tx + 64];
        ull xp3 = Xp[tx + 96];
        float4 wa = *(const float4*)(Ws + i * 72 + o0);
        float4 wb = *(const float4*)(Ws + i * 72 + o0 + 4);
        float wv[8] = {wa.x, wa.y, wa.z, wa.w, wb.x, wb.y, wb.z, wb.w};
#pragma unroll
        for (int oo = 0; oo < 8; oo++) {
            ull wp = bc2(wv[oo]);
            acc[oo][0] = ffma2(xp0, wp, acc[oo][0]);
            acc[oo][1] = ffma2(xp1, wp, acc[oo][1]);
            acc[oo][2] = ffma2(xp2, wp, acc[oo][2]);
            acc[oo][3] = ffma2(xp3, wp, acc[oo][3]);
        }
    }

    // spectral: packed rotation recurrence over x-pairs
    ull rot_re[4], rot_im[4], rtr_re[4], rtr_im[4];
#pragma unroll
    for (int p = 0; p < 4; p++) {
        rot_re[p] = bc2(1.f);
        rot_im[p] = 0ull;
        float2 t0 = tws[2 * tx + 64 * p];
        float2 t1 = tws[2 * tx + 64 * p + 1];
        rtr_re[p] = pk2(t0.x, t1.x);
        rtr_im[p] = pk2(t0.y, t1.y);
    }
#pragma unroll 4
    for (int kx = 0; kx < 20; kx++) {
#pragma unroll
        for (int oo = 0; oo < 8; oo++) {
            float2 tv = T2s[(o0 + oo) * 20 + kx];
            ull tvx = bc2(tv.x);
            ull ntvy = bc2(-tv.y);
#pragma unroll
            for (int p = 0; p < 4; p++) {
                acc[oo][p] = ffma2(rot_re[p], tvx, acc[oo][p]);
                acc[oo][p] = ffma2(rot_im[p], ntvy, acc[oo][p]);
            }
        }
#pragma unroll
        for (int p = 0; p < 4; p++) {
            ull t1 = fmul2(rot_re[p], rtr_re[p]);
            ull nrtr = fmul2(rot_im[p], rtr_im[p]);
            ull nre = ffma2(nrtr, bc2(-1.f), t1);
            ull t2 = fmul2(rot_re[p], rtr_im[p]);
            ull nim = ffma2(rot_im[p], rtr_re[p], t2);
            rot_re[p] = nre;
            rot_im[p] = nim;
        }
    }

#pragma unroll
    for (int oo = 0; oo < 8; oo++) {
        size_t ob = (((size_t)(b * 64 + o0 + oo)) * 256 + y) * 256;
#pragma unroll
        for (int p = 0; p < 4; p++) {
            float lo, hi;
            upk2(acc[oo][p], lo, hi);
            float2 s = make_float2(gelu_tanh(lo), gelu_tanh(hi));
            *(float2*)(out + ob + 2 * tx + 64 * p) = s;
        }
    }
}

extern "C" void kernel_launch(void* const* d_in, const int* in_sizes, int n_in,
                              void* d_out, int out_size) {
    const float* x  = (const float*)d_in[0];
    const float* wr = (const float*)d_in[1];
    const float* wi = (const float*)d_in[2];
    const float* cw = (const float*)d_in[3];
    const float* cb = (const float*)d_in[4];
    float* out = (float*)d_out;

    size_t smemBytes = (size_t)(64 * 256 + 64 * 72) * sizeof(float) +
                       (size_t)(64 * 20 + 256) * sizeof(float2);   // 96256 B
    cudaFuncSetAttribute(k_final, cudaFuncAttributeMaxDynamicSharedMemorySize, (int)smemBytes);

    k_init<<<1, 256>>>();
    k_wt<<<64 * 8, 256>>>(wr, wi);               // weight transpose (runs concurrently w/ fwdx path)
    k_fwdx<<<Bn * Cn * Hn / 256, 256>>>(x);
    k_fwdy<<<Bn * Cn, 256>>>();
    k_mix<<<M0 * M1, 256>>>();
    k_invy<<<Bn * Cn, 256>>>();
    k_final<<<Bn * Hn, 256, smemBytes>>>(x, cw, cb, out);
}